// round 2
// baseline (speedup 1.0000x reference)
#include <cuda_runtime.h>
#include <math_constants.h>

// ChamferLoss: B=4, N=8192, M=8192, D=3, K=1
// out = mean over 32768 queries of clamp(min_m ||q - r_m||^2, 0)

#define MREF     8192
#define NQ       32768            // B*N
#define CHUNK    2048
#define NCHUNK   (MREF / CHUNK)   // 4
#define TPB      128
#define QBLOCKS  (NQ / TPB)       // 256
#define RBLK     64

// Scratch (no allocations allowed in kernel_launch)
__device__ float4 g_refmod[MREF];
__device__ float  g_partial[NCHUNK * NQ];
__device__ float  g_bsum[RBLK];

// ---------------------------------------------------------------------------
// Kernel 0: precompute per-ref (-2rx, -2ry, -2rz, |r|^2)
// ---------------------------------------------------------------------------
__global__ void prep_kernel(const float* __restrict__ ref) {
    int m = blockIdx.x * blockDim.x + threadIdx.x;
    if (m < MREF) {
        float x = ref[3 * m + 0];
        float y = ref[3 * m + 1];
        float z = ref[3 * m + 2];
        g_refmod[m] = make_float4(-2.0f * x, -2.0f * y, -2.0f * z,
                                  x * x + y * y + z * z);
    }
}

// ---------------------------------------------------------------------------
// Kernel 1: main — each thread = 1 query vs one 2048-ref chunk.
// Inner loop per ref: 3 FFMA + 1 FMNMX. 8 independent min accumulators
// break the serial FMNMX dependency chain.
// ---------------------------------------------------------------------------
__global__ void __launch_bounds__(TPB) chamfer_main(const float* __restrict__ query) {
    __shared__ float4 s_ref[CHUNK];   // 32 KB

    const int tid   = threadIdx.x;
    const int chunk = blockIdx.y;

    // Cooperative chunk load (16B per thread per iter, coalesced)
    const float4* __restrict__ src = g_refmod + chunk * CHUNK;
    #pragma unroll
    for (int i = 0; i < CHUNK / TPB; i++) {
        s_ref[i * TPB + tid] = src[i * TPB + tid];
    }

    const int qi = blockIdx.x * TPB + tid;
    const float qx = query[3 * qi + 0];
    const float qy = query[3 * qi + 1];
    const float qz = query[3 * qi + 2];
    const float q2 = qx * qx + qy * qy + qz * qz;

    __syncthreads();

    float acc[8];
    #pragma unroll
    for (int u = 0; u < 8; u++) acc[u] = CUDART_INF_F;

    for (int j = 0; j < CHUNK; j += 8) {
        #pragma unroll
        for (int u = 0; u < 8; u++) {
            float4 r = s_ref[j + u];   // broadcast across warp, conflict-free
            // t = |r|^2 - 2 q.r
            float t = fmaf(qx, r.x, fmaf(qy, r.y, fmaf(qz, r.z, r.w)));
            acc[u] = fminf(acc[u], t);
        }
    }

    float m01 = fminf(acc[0], acc[1]);
    float m23 = fminf(acc[2], acc[3]);
    float m45 = fminf(acc[4], acc[5]);
    float m67 = fminf(acc[6], acc[7]);
    float mn  = fminf(fminf(m01, m23), fminf(m45, m67));

    // clamp commutes with min over chunks (monotone)
    g_partial[chunk * NQ + qi] = fmaxf(q2 + mn, 0.0f);
}

// ---------------------------------------------------------------------------
// Kernel 2: per-block reduce — min over 4 chunks, then sum 512 queries/block.
// Deterministic tree reduction.
// ---------------------------------------------------------------------------
__global__ void __launch_bounds__(256) reduce1_kernel() {
    __shared__ float s[256];
    const int tid   = threadIdx.x;
    const int qbase = blockIdx.x * 512;

    float sum = 0.0f;
    #pragma unroll
    for (int k = 0; k < 2; k++) {
        int q = qbase + k * 256 + tid;
        float v = g_partial[0 * NQ + q];
        #pragma unroll
        for (int c = 1; c < NCHUNK; c++) {
            v = fminf(v, g_partial[c * NQ + q]);
        }
        sum += v;
    }
    s[tid] = sum;
    __syncthreads();

    #pragma unroll
    for (int stride = 128; stride >= 1; stride >>= 1) {
        if (tid < stride) s[tid] += s[tid + stride];
        __syncthreads();
    }
    if (tid == 0) g_bsum[blockIdx.x] = s[0];
}

// ---------------------------------------------------------------------------
// Kernel 3: final sum of 64 block partials -> mean -> d_out[0]
// ---------------------------------------------------------------------------
__global__ void __launch_bounds__(64) reduce2_kernel(float* __restrict__ out) {
    __shared__ float s[64];
    const int tid = threadIdx.x;
    s[tid] = g_bsum[tid];
    __syncthreads();
    if (tid < 32) {
        float v = s[tid] + s[tid + 32];
        #pragma unroll
        for (int off = 16; off >= 1; off >>= 1) {
            v += __shfl_down_sync(0xFFFFFFFFu, v, off);
        }
        if (tid == 0) out[0] = v * (1.0f / (float)NQ);
    }
}

// ---------------------------------------------------------------------------
extern "C" void kernel_launch(void* const* d_in, const int* in_sizes, int n_in,
                              void* d_out, int out_size) {
    const float* query = (const float*)d_in[0];   // [4, 8192, 3] f32
    const float* ref   = (const float*)d_in[1];   // [8192, 3] f32
    (void)in_sizes; (void)n_in; (void)out_size;   // K == 1 (fixed shapes)
    float* out = (float*)d_out;

    prep_kernel<<<(MREF + 127) / 128, 128>>>(ref);
    chamfer_main<<<dim3(QBLOCKS, NCHUNK), TPB>>>(query);
    reduce1_kernel<<<RBLK, 256>>>();
    reduce2_kernel<<<1, 64>>>(out);
}

// round 6
// speedup vs baseline: 1.5138x; 1.5138x over previous
#include <cuda_runtime.h>
#include <math_constants.h>
#include <cstdint>

// ChamferLoss: B=4, N=8192, M=8192, D=3, K=1
// out = mean over 32768 queries of clamp(min_m ||q - r_m||^2, 0)
//
// Strategy: d^2 = |q|^2 + (|r|^2 - 2 q.r). Precompute per-ref (-2r, |r|^2) in
// SoA. Inner loop uses packed fma.rn.f32x2 (FFMA2) over ref PAIRS — two fp32
// FMAs per fma-pipe issue — and 2 queries per thread to amortize LDS.

#define MREF     8192
#define NQ       32768
#define CHUNK    1024
#define NCHUNK   (MREF / CHUNK)     // 8
#define TPB      128
#define QPT      2                  // queries per thread
#define QPB      (TPB * QPT)        // 256
#define QBLOCKS  (NQ / QPB)         // 128
#define RBLK     64

__device__ __align__(16) float g_rx[MREF];
__device__ __align__(16) float g_ry[MREF];
__device__ __align__(16) float g_rz[MREF];
__device__ __align__(16) float g_rw[MREF];
__device__ float g_partial[NCHUNK * NQ];
__device__ float g_bsum[RBLK];

// ---------- packed f32x2 helpers ----------
__device__ __forceinline__ uint64_t pack_dup(float v) {
    uint64_t r;
    asm("mov.b64 %0, {%1, %1};" : "=l"(r) : "f"(v));
    return r;
}
__device__ __forceinline__ uint64_t fma2(uint64_t a, uint64_t b, uint64_t c) {
    uint64_t d;
    asm("fma.rn.f32x2 %0, %1, %2, %3;" : "=l"(d) : "l"(a), "l"(b), "l"(c));
    return d;
}
__device__ __forceinline__ void unpack2(uint64_t v, float& lo, float& hi) {
    asm("mov.b64 {%0, %1}, %2;" : "=f"(lo), "=f"(hi) : "l"(v));
}
// 16B shared load -> two f32x2 pairs (no packing MOVs needed)
__device__ __forceinline__ void lds_2x64(uint32_t addr, uint64_t& a, uint64_t& b) {
    asm("ld.shared.v2.b64 {%0, %1}, [%2];" : "=l"(a), "=l"(b) : "r"(addr));
}

// ---------------------------------------------------------------------------
// Kernel 0: precompute SoA (-2rx, -2ry, -2rz, |r|^2)
// ---------------------------------------------------------------------------
__global__ void prep_kernel(const float* __restrict__ ref) {
    int m = blockIdx.x * blockDim.x + threadIdx.x;
    if (m < MREF) {
        float x = ref[3 * m + 0];
        float y = ref[3 * m + 1];
        float z = ref[3 * m + 2];
        g_rx[m] = -2.0f * x;
        g_ry[m] = -2.0f * y;
        g_rz[m] = -2.0f * z;
        g_rw[m] = x * x + y * y + z * z;
    }
}

// ---------------------------------------------------------------------------
// Kernel 1: main. Each thread: 2 queries vs one 1024-ref chunk.
// Per 4-ref group: 4x LDS.128 (x/y/z/w quads) + 12 FFMA2 + 8 FMNMX,
// covering 8 query/ref pairs -> 1.5 fma-pipe issues per pair.
// ---------------------------------------------------------------------------
__global__ void __launch_bounds__(TPB) chamfer_main(const float* __restrict__ query) {
    __shared__ __align__(16) float s_x[CHUNK];
    __shared__ __align__(16) float s_y[CHUNK];
    __shared__ __align__(16) float s_z[CHUNK];
    __shared__ __align__(16) float s_w[CHUNK];

    const int tid   = threadIdx.x;
    const int chunk = blockIdx.y;
    const int base  = chunk * CHUNK;

    // Cooperative SoA load: 1024 floats per array, float4 per thread per iter
    #pragma unroll
    for (int i = 0; i < CHUNK / (TPB * 4); i++) {       // 2 iters
        int idx = (i * TPB + tid) * 4;
        *(float4*)&s_x[idx] = *(const float4*)&g_rx[base + idx];
        *(float4*)&s_y[idx] = *(const float4*)&g_ry[base + idx];
        *(float4*)&s_z[idx] = *(const float4*)&g_rz[base + idx];
        *(float4*)&s_w[idx] = *(const float4*)&g_rw[base + idx];
    }

    // Two queries per thread (coalesced: tid and tid+TPB)
    const int q0 = blockIdx.x * QPB + tid;
    const int q1 = q0 + TPB;

    const float ax = query[3 * q0 + 0], ay = query[3 * q0 + 1], az = query[3 * q0 + 2];
    const float bx = query[3 * q1 + 0], by = query[3 * q1 + 1], bz = query[3 * q1 + 2];
    const float a2 = ax * ax + ay * ay + az * az;
    const float b2 = bx * bx + by * by + bz * bz;

    const uint64_t pax = pack_dup(ax), pay = pack_dup(ay), paz = pack_dup(az);
    const uint64_t pbx = pack_dup(bx), pby = pack_dup(by), pbz = pack_dup(bz);

    const uint32_t adr_x = (uint32_t)__cvta_generic_to_shared(s_x);
    const uint32_t adr_y = (uint32_t)__cvta_generic_to_shared(s_y);
    const uint32_t adr_z = (uint32_t)__cvta_generic_to_shared(s_z);
    const uint32_t adr_w = (uint32_t)__cvta_generic_to_shared(s_w);

    __syncthreads();

    float accA[4], accB[4];
    #pragma unroll
    for (int u = 0; u < 4; u++) { accA[u] = CUDART_INF_F; accB[u] = CUDART_INF_F; }

    #pragma unroll 2
    for (int j = 0; j < CHUNK; j += 4) {
        const uint32_t off = j * 4;   // bytes, 16B aligned
        uint64_t x01, x23, y01, y23, z01, z23, w01, w23;
        lds_2x64(adr_x + off, x01, x23);
        lds_2x64(adr_y + off, y01, y23);
        lds_2x64(adr_z + off, z01, z23);
        lds_2x64(adr_w + off, w01, w23);

        // t = w + z*qz + y*qy + x*qx   (= |r|^2 - 2 q.r), packed over ref pairs
        uint64_t tA01 = fma2(pax, x01, fma2(pay, y01, fma2(paz, z01, w01)));
        uint64_t tA23 = fma2(pax, x23, fma2(pay, y23, fma2(paz, z23, w23)));
        uint64_t tB01 = fma2(pbx, x01, fma2(pby, y01, fma2(pbz, z01, w01)));
        uint64_t tB23 = fma2(pbx, x23, fma2(pby, y23, fma2(pbz, z23, w23)));

        float lo, hi;
        unpack2(tA01, lo, hi); accA[0] = fminf(accA[0], lo); accA[1] = fminf(accA[1], hi);
        unpack2(tA23, lo, hi); accA[2] = fminf(accA[2], lo); accA[3] = fminf(accA[3], hi);
        unpack2(tB01, lo, hi); accB[0] = fminf(accB[0], lo); accB[1] = fminf(accB[1], hi);
        unpack2(tB23, lo, hi); accB[2] = fminf(accB[2], lo); accB[3] = fminf(accB[3], hi);
    }

    const float mA = fminf(fminf(accA[0], accA[1]), fminf(accA[2], accA[3]));
    const float mB = fminf(fminf(accB[0], accB[1]), fminf(accB[2], accB[3]));

    // clamp commutes with min over chunks (monotone)
    g_partial[chunk * NQ + q0] = fmaxf(a2 + mA, 0.0f);
    g_partial[chunk * NQ + q1] = fmaxf(b2 + mB, 0.0f);
}

// ---------------------------------------------------------------------------
// Kernel 2: min over 8 chunks, then deterministic per-block sum (512 q/block)
// ---------------------------------------------------------------------------
__global__ void __launch_bounds__(256) reduce1_kernel() {
    __shared__ float s[256];
    const int tid   = threadIdx.x;
    const int qbase = blockIdx.x * 512;

    float sum = 0.0f;
    #pragma unroll
    for (int k = 0; k < 2; k++) {
        int q = qbase + k * 256 + tid;
        float v = g_partial[0 * NQ + q];
        #pragma unroll
        for (int c = 1; c < NCHUNK; c++) {
            v = fminf(v, g_partial[c * NQ + q]);
        }
        sum += v;
    }
    s[tid] = sum;
    __syncthreads();

    #pragma unroll
    for (int stride = 128; stride >= 1; stride >>= 1) {
        if (tid < stride) s[tid] += s[tid + stride];
        __syncthreads();
    }
    if (tid == 0) g_bsum[blockIdx.x] = s[0];
}

// ---------------------------------------------------------------------------
// Kernel 3: final sum of 64 partials -> mean
// ---------------------------------------------------------------------------
__global__ void __launch_bounds__(64) reduce2_kernel(float* __restrict__ out) {
    __shared__ float s[64];
    const int tid = threadIdx.x;
    s[tid] = g_bsum[tid];
    __syncthreads();
    if (tid < 32) {
        float v = s[tid] + s[tid + 32];
        #pragma unroll
        for (int off = 16; off >= 1; off >>= 1) {
            v += __shfl_down_sync(0xFFFFFFFFu, v, off);
        }
        if (tid == 0) out[0] = v * (1.0f / (float)NQ);
    }
}

// ---------------------------------------------------------------------------
extern "C" void kernel_launch(void* const* d_in, const int* in_sizes, int n_in,
                              void* d_out, int out_size) {
    const float* query = (const float*)d_in[0];   // [4, 8192, 3] f32
    const float* ref   = (const float*)d_in[1];   // [8192, 3] f32
    (void)in_sizes; (void)n_in; (void)out_size;   // K == 1, fixed shapes
    float* out = (float*)d_out;

    prep_kernel<<<(MREF + 127) / 128, 128>>>(ref);
    chamfer_main<<<dim3(QBLOCKS, NCHUNK), TPB>>>(query);
    reduce1_kernel<<<RBLK, 256>>>();
    reduce2_kernel<<<1, 64>>>(out);
}

// round 7
// speedup vs baseline: 1.5786x; 1.0428x over previous
#include <cuda_runtime.h>
#include <math_constants.h>
#include <cstdint>

// ChamferLoss: B=4, N=8192, M=8192, D=3, K=1 — single fused kernel.
// d^2 = |q|^2 + (|r|^2 - 2 q.r); per-chunk refmod computed in-kernel into
// SMEM SoA; inner loop = packed fma.rn.f32x2 over ref pairs, 2 queries/thread;
// cross-chunk min + global mean via threadfence-reduction ticket pattern.

#define MREF     8192
#define NQ       32768
#define CHUNK    1024
#define NCHUNK   (MREF / CHUNK)     // 8
#define TPB      128
#define QPT      2
#define QPB      (TPB * QPT)        // 256
#define QBLOCKS  (NQ / QPB)         // 128
#define GRID     (QBLOCKS * NCHUNK) // 1024
#define STAGE2   64                 // last 64 tickets do stage-2 slices
#define S2_Q     (NQ / STAGE2)      // 512 queries per slice
#define S2_QPT   (S2_Q / TPB)       // 4

__device__ float    g_partial[NCHUNK * NQ];   // clamped per-chunk mins
__device__ float    g_bsum[STAGE2];
__device__ unsigned g_done  = 0;
__device__ unsigned g_done2 = 0;

// ---------- packed f32x2 helpers ----------
__device__ __forceinline__ uint64_t pack_dup(float v) {
    uint64_t r;
    asm("mov.b64 %0, {%1, %1};" : "=l"(r) : "f"(v));
    return r;
}
__device__ __forceinline__ uint64_t fma2(uint64_t a, uint64_t b, uint64_t c) {
    uint64_t d;
    asm("fma.rn.f32x2 %0, %1, %2, %3;" : "=l"(d) : "l"(a), "l"(b), "l"(c));
    return d;
}
__device__ __forceinline__ void unpack2(uint64_t v, float& lo, float& hi) {
    asm("mov.b64 {%0, %1}, %2;" : "=f"(lo), "=f"(hi) : "l"(v));
}
__device__ __forceinline__ void lds_2x64(uint32_t addr, uint64_t& a, uint64_t& b) {
    asm("ld.shared.v2.b64 {%0, %1}, [%2];" : "=l"(a), "=l"(b) : "r"(addr));
}

__global__ void __launch_bounds__(TPB, 8)
chamfer_fused(const float* __restrict__ query,
              const float* __restrict__ ref,
              float* __restrict__ out) {
    __shared__ __align__(16) float s_x[CHUNK];
    __shared__ __align__(16) float s_y[CHUNK];
    __shared__ __align__(16) float s_z[CHUNK];
    __shared__ __align__(16) float s_w[CHUNK];
    __shared__ float s_red[TPB];
    __shared__ unsigned s_ticket;

    const int tid   = threadIdx.x;
    const int chunk = blockIdx.y;
    const int base  = chunk * CHUNK;

    // ---- inline refmod: (-2x, -2y, -2z, |r|^2) for this chunk ----
    #pragma unroll
    for (int p = 0; p < CHUNK / TPB; p++) {            // 8 points/thread
        const int i = p * TPB + tid;
        const int m = base + i;
        const float x = ref[3 * m + 0];
        const float y = ref[3 * m + 1];
        const float z = ref[3 * m + 2];
        s_x[i] = -2.0f * x;
        s_y[i] = -2.0f * y;
        s_z[i] = -2.0f * z;
        s_w[i] = x * x + y * y + z * z;
    }

    // ---- two queries per thread (coalesced: tid and tid+TPB) ----
    const int q0 = blockIdx.x * QPB + tid;
    const int q1 = q0 + TPB;

    const float ax = query[3 * q0 + 0], ay = query[3 * q0 + 1], az = query[3 * q0 + 2];
    const float bx = query[3 * q1 + 0], by = query[3 * q1 + 1], bz = query[3 * q1 + 2];
    const float a2 = ax * ax + ay * ay + az * az;
    const float b2 = bx * bx + by * by + bz * bz;

    const uint64_t pax = pack_dup(ax), pay = pack_dup(ay), paz = pack_dup(az);
    const uint64_t pbx = pack_dup(bx), pby = pack_dup(by), pbz = pack_dup(bz);

    const uint32_t adr_x = (uint32_t)__cvta_generic_to_shared(s_x);
    const uint32_t adr_y = (uint32_t)__cvta_generic_to_shared(s_y);
    const uint32_t adr_z = (uint32_t)__cvta_generic_to_shared(s_z);
    const uint32_t adr_w = (uint32_t)__cvta_generic_to_shared(s_w);

    __syncthreads();

    // ---- main loop: per 4-ref group x 2 queries: 4 LDS.128 + 12 FFMA2 + 8 FMNMX
    float accA[4], accB[4];
    #pragma unroll
    for (int u = 0; u < 4; u++) { accA[u] = CUDART_INF_F; accB[u] = CUDART_INF_F; }

    #pragma unroll 2
    for (int j = 0; j < CHUNK; j += 4) {
        const uint32_t off = j * 4;
        uint64_t x01, x23, y01, y23, z01, z23, w01, w23;
        lds_2x64(adr_x + off, x01, x23);
        lds_2x64(adr_y + off, y01, y23);
        lds_2x64(adr_z + off, z01, z23);
        lds_2x64(adr_w + off, w01, w23);

        uint64_t tA01 = fma2(pax, x01, fma2(pay, y01, fma2(paz, z01, w01)));
        uint64_t tA23 = fma2(pax, x23, fma2(pay, y23, fma2(paz, z23, w23)));
        uint64_t tB01 = fma2(pbx, x01, fma2(pby, y01, fma2(pbz, z01, w01)));
        uint64_t tB23 = fma2(pbx, x23, fma2(pby, y23, fma2(pbz, z23, w23)));

        float lo, hi;
        unpack2(tA01, lo, hi); accA[0] = fminf(accA[0], lo); accA[1] = fminf(accA[1], hi);
        unpack2(tA23, lo, hi); accA[2] = fminf(accA[2], lo); accA[3] = fminf(accA[3], hi);
        unpack2(tB01, lo, hi); accB[0] = fminf(accB[0], lo); accB[1] = fminf(accB[1], hi);
        unpack2(tB23, lo, hi); accB[2] = fminf(accB[2], lo); accB[3] = fminf(accB[3], hi);
    }

    const float mA = fminf(fminf(accA[0], accA[1]), fminf(accA[2], accA[3]));
    const float mB = fminf(fminf(accB[0], accB[1]), fminf(accB[2], accB[3]));

    // clamp commutes with min over chunks (min is monotone)
    g_partial[chunk * NQ + q0] = fmaxf(a2 + mA, 0.0f);
    g_partial[chunk * NQ + q1] = fmaxf(b2 + mB, 0.0f);

    // ---- ticket: detect the last STAGE2 CTAs ----
    __syncthreads();
    if (tid == 0) {
        __threadfence();
        s_ticket = atomicAdd(&g_done, 1u);
    }
    __syncthreads();
    const unsigned ticket = s_ticket;

    if (ticket < GRID - STAGE2) return;

    // ---- stage 2: wait for all CTAs, then reduce a 512-query slice ----
    if (tid == 0) {
        volatile unsigned* vd = &g_done;
        while (*vd < (unsigned)GRID) { __nanosleep(64); }
    }
    __syncthreads();
    __threadfence();

    const int slice = (int)ticket - (GRID - STAGE2);    // 0..63

    float sum = 0.0f;
    #pragma unroll
    for (int k = 0; k < S2_QPT; k++) {
        const int q = slice * S2_Q + k * TPB + tid;
        float v = g_partial[0 * NQ + q];
        #pragma unroll
        for (int c = 1; c < NCHUNK; c++) {
            v = fminf(v, g_partial[c * NQ + q]);
        }
        sum += v;
    }
    s_red[tid] = sum;
    __syncthreads();

    #pragma unroll
    for (int stride = TPB / 2; stride >= 1; stride >>= 1) {
        if (tid < stride) s_red[tid] += s_red[tid + stride];
        __syncthreads();
    }

    if (tid == 0) {
        g_bsum[slice] = s_red[0];
        __threadfence();
        const unsigned t2 = atomicAdd(&g_done2, 1u);
        if (t2 == STAGE2 - 1) {
            __threadfence();
            float total = 0.0f;
            #pragma unroll
            for (int i = 0; i < STAGE2; i++) total += g_bsum[i];
            out[0] = total * (1.0f / (float)NQ);
            // reset counters for next launch/replay
            g_done  = 0u;
            g_done2 = 0u;
            __threadfence();
        }
    }
}

// ---------------------------------------------------------------------------
extern "C" void kernel_launch(void* const* d_in, const int* in_sizes, int n_in,
                              void* d_out, int out_size) {
    const float* query = (const float*)d_in[0];   // [4, 8192, 3] f32
    const float* ref   = (const float*)d_in[1];   // [8192, 3] f32
    (void)in_sizes; (void)n_in; (void)out_size;   // K == 1, fixed shapes
    float* out = (float*)d_out;

    chamfer_fused<<<dim3(QBLOCKS, NCHUNK), TPB>>>(query, ref, out);
}

// round 8
// speedup vs baseline: 1.7251x; 1.0928x over previous
#include <cuda_runtime.h>
#include <math_constants.h>
#include <cstdint>

// ChamferLoss: B=4, N=8192, M=8192, D=3, K=1 — single fused kernel.
// d^2 = |q|^2 + (|r|^2 - 2 q.r). Per-chunk refmod (-2r, |r|^2) built in SMEM
// (SoA, one array). Inner loop: packed fma.rn.f32x2 over ref pairs, FOUR
// queries per thread (LDS amortized 2x vs R6). Cross-chunk min + mean via
// threadfence-reduction ticket pattern.

#define MREF     8192
#define NQ       32768
#define CHUNK    512
#define NCHUNK   (MREF / CHUNK)     // 16
#define TPB      128
#define QPT      4
#define QPB      (TPB * QPT)        // 512
#define QBLOCKS  (NQ / QPB)         // 64
#define GRID     (QBLOCKS * NCHUNK) // 1024
#define STAGE2   64
#define S2_Q     (NQ / STAGE2)      // 512
#define S2_QPT   (S2_Q / TPB)       // 4

#define XOFF     0
#define YOFF     (CHUNK * 4)        // byte offsets inside s_ref
#define ZOFF     (2 * CHUNK * 4)
#define WOFF     (3 * CHUNK * 4)

__device__ float    g_partial[NCHUNK * NQ];
__device__ float    g_bsum[STAGE2];
__device__ unsigned g_done  = 0;
__device__ unsigned g_done2 = 0;

// ---------- packed f32x2 helpers ----------
__device__ __forceinline__ uint64_t pack_dup(float v) {
    uint64_t r;
    asm("mov.b64 %0, {%1, %1};" : "=l"(r) : "f"(v));
    return r;
}
__device__ __forceinline__ uint64_t fma2(uint64_t a, uint64_t b, uint64_t c) {
    uint64_t d;
    asm("fma.rn.f32x2 %0, %1, %2, %3;" : "=l"(d) : "l"(a), "l"(b), "l"(c));
    return d;
}
__device__ __forceinline__ void unpack2(uint64_t v, float& lo, float& hi) {
    asm("mov.b64 {%0, %1}, %2;" : "=f"(lo), "=f"(hi) : "l"(v));
}
__device__ __forceinline__ void lds_2x64(uint32_t addr, uint64_t& a, uint64_t& b) {
    asm("ld.shared.v2.b64 {%0, %1}, [%2];" : "=l"(a), "=l"(b) : "r"(addr));
}

__global__ void __launch_bounds__(TPB, 7)
chamfer_fused(const float* __restrict__ query,
              const float* __restrict__ ref,
              float* __restrict__ out) {
    __shared__ __align__(16) float s_ref[4 * CHUNK];   // x | y | z | w regions
    __shared__ float s_red[TPB];
    __shared__ unsigned s_ticket;

    const int tid   = threadIdx.x;
    const int chunk = blockIdx.y;
    const int base  = chunk * CHUNK;

    // ---- inline refmod for this chunk ----
    #pragma unroll
    for (int p = 0; p < CHUNK / TPB; p++) {            // 4 points/thread
        const int i = p * TPB + tid;
        const int m = base + i;
        const float x = ref[3 * m + 0];
        const float y = ref[3 * m + 1];
        const float z = ref[3 * m + 2];
        s_ref[i]             = -2.0f * x;
        s_ref[CHUNK + i]     = -2.0f * y;
        s_ref[2 * CHUNK + i] = -2.0f * z;
        s_ref[3 * CHUNK + i] = x * x + y * y + z * z;
    }

    // ---- four queries per thread (coalesced: tid + k*TPB) ----
    const int qbase = blockIdx.x * QPB + tid;

    uint64_t pqx[QPT], pqy[QPT], pqz[QPT];
    float    q2[QPT];
    #pragma unroll
    for (int k = 0; k < QPT; k++) {
        const int q = qbase + k * TPB;
        const float x = query[3 * q + 0];
        const float y = query[3 * q + 1];
        const float z = query[3 * q + 2];
        q2[k]  = x * x + y * y + z * z;
        pqx[k] = pack_dup(x);
        pqy[k] = pack_dup(y);
        pqz[k] = pack_dup(z);
    }

    const uint32_t adr = (uint32_t)__cvta_generic_to_shared(s_ref);

    __syncthreads();

    // ---- main loop: per 4-ref group x 4 queries:
    //      4 LDS.128 + 24 FFMA2 + 16 FMNMX  -> 16 query/ref pairs
    float acc0[QPT], acc1[QPT];
    #pragma unroll
    for (int k = 0; k < QPT; k++) { acc0[k] = CUDART_INF_F; acc1[k] = CUDART_INF_F; }

    #pragma unroll 1
    for (int j = 0; j < CHUNK; j += 4) {
        const uint32_t off = adr + j * 4;
        uint64_t x01, x23, y01, y23, z01, z23, w01, w23;
        lds_2x64(off + XOFF, x01, x23);
        lds_2x64(off + YOFF, y01, y23);
        lds_2x64(off + ZOFF, z01, z23);
        lds_2x64(off + WOFF, w01, w23);

        #pragma unroll
        for (int k = 0; k < QPT; k++) {
            uint64_t t01 = fma2(pqx[k], x01, fma2(pqy[k], y01, fma2(pqz[k], z01, w01)));
            uint64_t t23 = fma2(pqx[k], x23, fma2(pqy[k], y23, fma2(pqz[k], z23, w23)));
            float lo, hi;
            unpack2(t01, lo, hi);
            acc0[k] = fminf(acc0[k], lo);
            acc1[k] = fminf(acc1[k], hi);
            unpack2(t23, lo, hi);
            acc0[k] = fminf(acc0[k], lo);
            acc1[k] = fminf(acc1[k], hi);
        }
    }

    // clamp commutes with min over chunks (min is monotone)
    #pragma unroll
    for (int k = 0; k < QPT; k++) {
        const float m = fminf(acc0[k], acc1[k]);
        g_partial[chunk * NQ + qbase + k * TPB] = fmaxf(q2[k] + m, 0.0f);
    }

    // ---- ticket: last STAGE2 CTAs do the global reduction ----
    __syncthreads();
    if (tid == 0) {
        __threadfence();
        s_ticket = atomicAdd(&g_done, 1u);
    }
    __syncthreads();
    const unsigned ticket = s_ticket;

    if (ticket < GRID - STAGE2) return;

    if (tid == 0) {
        volatile unsigned* vd = &g_done;
        while (*vd < (unsigned)GRID) { __nanosleep(64); }
    }
    __syncthreads();
    __threadfence();

    const int slice = (int)ticket - (GRID - STAGE2);    // 0..63

    float sum = 0.0f;
    #pragma unroll
    for (int k = 0; k < S2_QPT; k++) {
        const int q = slice * S2_Q + k * TPB + tid;
        float v = g_partial[0 * NQ + q];
        #pragma unroll
        for (int c = 1; c < NCHUNK; c++) {
            v = fminf(v, g_partial[c * NQ + q]);
        }
        sum += v;
    }
    s_red[tid] = sum;
    __syncthreads();

    #pragma unroll
    for (int stride = TPB / 2; stride >= 1; stride >>= 1) {
        if (tid < stride) s_red[tid] += s_red[tid + stride];
        __syncthreads();
    }

    if (tid == 0) {
        g_bsum[slice] = s_red[0];
        __threadfence();
        const unsigned t2 = atomicAdd(&g_done2, 1u);
        if (t2 == STAGE2 - 1) {
            __threadfence();
            float total = 0.0f;
            #pragma unroll
            for (int i = 0; i < STAGE2; i++) total += g_bsum[i];
            out[0] = total * (1.0f / (float)NQ);
            g_done  = 0u;
            g_done2 = 0u;
            __threadfence();
        }
    }
}

// ---------------------------------------------------------------------------
extern "C" void kernel_launch(void* const* d_in, const int* in_sizes, int n_in,
                              void* d_out, int out_size) {
    const float* query = (const float*)d_in[0];   // [4, 8192, 3] f32
    const float* ref   = (const float*)d_in[1];   // [8192, 3] f32
    (void)in_sizes; (void)n_in; (void)out_size;   // K == 1, fixed shapes
    float* out = (float*)d_out;

    chamfer_fused<<<dim3(QBLOCKS, NCHUNK), TPB>>>(query, ref, out);
}